// round 14
// baseline (speedup 1.0000x reference)
#include <cuda_runtime.h>
#include <cuda_fp16.h>
#include <math.h>
#include <stdint.h>

#define B_  2
#define T_  2048
#define C_  1024
#define H_  16
#define HD  64
#define BT  (B_*T_)      // 4096
#define C3  (3*C_)       // 3072
#define C5  (5*C_)       // 5120
#define NC  (T_/HD)      // 32 chunks
#define BH  (B_*H_)      // 32

// ---------------- scratch (device globals) ----------------
__device__ __half g_qkv16[BT*(size_t)C3];         // q,k,v fp16 (stride 3C), rotary applied
__device__ float  g_W [BH*(size_t)NC*HD*HD];
__device__ __half g_S16[BH*(size_t)NC*HD*HD];     // scanned states fp16
__device__ float  g_z [BT*(size_t)C_];            // silu(gate) fp32
__device__ float  g_ffout[BT*(size_t)C_];         // ff GEMM result
__device__ float4 g_rot [T_*(size_t)512];         // (cq,sq,ck,sk) per (t,j)
// single fp16 operands
__device__ __half g_a_q1  [BT*(size_t)C_];        // rms-normed x
__device__ __half g_b_qkv1[C5*(size_t)C_];
__device__ __half g_a_x1  [BT*(size_t)C_];        // raw x
__device__ __half g_b_gat1[C_*(size_t)C_];
__device__ __half g_a_prj1[BT*(size_t)C_];
__device__ __half g_b_prj1[C_*(size_t)C_];
__device__ __half g_a_ff1 [BT*(size_t)2*C_];      // gelu(ff) fp16
__device__ __half g_b_ff1 [C_*(size_t)2*C_];

// ---------------- PTX helpers ----------------
__device__ __forceinline__ uint32_t smem_u32(const void* p) {
    uint32_t a;
    asm("{ .reg .u64 t; cvta.to.shared.u64 t, %1; cvt.u32.u64 %0, t; }" : "=r"(a) : "l"(p));
    return a;
}
#define CPA(dst, src)  asm volatile("cp.async.cg.shared.global [%0], [%1], 16;" :: "r"(dst), "l"(src) : "memory")
#define CPC()          asm volatile("cp.async.commit_group;" ::: "memory")
#define CPW(n)         asm volatile("cp.async.wait_group %0;" :: "n"(n) : "memory")
#define SWZ(o) ((o) ^ (((o) >> 3) & 0x70))

#define LDM_X4(r0, r1, r2, r3, a) \
    asm volatile("ldmatrix.sync.aligned.m8n8.x4.shared.b16 {%0,%1,%2,%3}, [%4];" \
        : "=r"(r0), "=r"(r1), "=r"(r2), "=r"(r3) : "r"(a))
#define LDM_X4T(r0, r1, r2, r3, a) \
    asm volatile("ldmatrix.sync.aligned.m8n8.x4.trans.shared.b16 {%0,%1,%2,%3}, [%4];" \
        : "=r"(r0), "=r"(r1), "=r"(r2), "=r"(r3) : "r"(a))

#define MMA_F16(d, a, b0, b1) \
    asm volatile("mma.sync.aligned.m16n8k16.row.col.f32.f16.f16.f32 " \
        "{%0,%1,%2,%3}, {%4,%5,%6,%7}, {%8,%9}, {%0,%1,%2,%3};" \
        : "+f"((d)[0]), "+f"((d)[1]), "+f"((d)[2]), "+f"((d)[3]) \
        : "r"((a)[0]), "r"((a)[1]), "r"((a)[2]), "r"((a)[3]), "r"(b0), "r"(b1))

// ---------------- warp-MMA fp16 NT GEMM (proven R4 mainloop) ----------------
// EPI 1: silu(v+bias[n]) -> fp32 Cout
// EPI 2: plain -> Cout
// EPI 3: v + bias[n] + aux0[o] + aux1[o] -> Cout
// EPI 4: gelu(v) -> fp16 osplit (row stride N)
// EPI 5: merged qkvff: n<2048 rotary -> fp16 osplit(stride C3); 2048..3071 pass -> osplit;
//        n>=3072 gelu -> fp16 ((half*)aux1) stride 2048
template<int EPI>
__global__ void __launch_bounds__(256, 1) mma_gemm(
    const __half* __restrict__ A, const __half* __restrict__ Bm,
    int Kp, int N, float* __restrict__ Cout,
    const float* __restrict__ bias, const float* __restrict__ aux0,
    const float* __restrict__ aux1, __half* __restrict__ osplit)
{
    extern __shared__ __align__(1024) char smem_raw[];
    const int S = 4;
    const uint32_t STAGE = 49152;   // A 16KB + B 32KB
    uint32_t sbase = (smem_u32(smem_raw) + 1023) & ~1023u;

    int tid = threadIdx.x;
    int wid = tid >> 5, lane = tid & 31;
    int warp_m = wid & 1, warp_n = wid >> 1;
    int bm = blockIdx.y << 7, bn = blockIdx.x << 8;

    const int nk = Kp >> 6;

    auto load_stage = [&](int s, int k) {
        uint32_t a_s = sbase + s * STAGE;
        uint32_t b_s = a_s + 16384u;
        const __half* Ag = A + (size_t)bm * Kp + (size_t)k * 64;
        const __half* Bg = Bm + (size_t)bn * Kp + (size_t)k * 64;
        #pragma unroll
        for (int q = 0; q < 4; q++) {
            int i = tid + (q << 8);
            int r = i >> 3, c = i & 7;
            uint32_t off = SWZ(r * 128 + c * 16);
            CPA(a_s + off, (const char*)(Ag + (size_t)r * Kp + c * 8));
        }
        #pragma unroll
        for (int q = 0; q < 8; q++) {
            int i = tid + (q << 8);
            int r = i >> 3, c = i & 7;
            uint32_t off = SWZ(r * 128 + c * 16);
            CPA(b_s + off, (const char*)(Bg + (size_t)r * Kp + c * 8));
        }
    };

    float acc[4][8][4];
    #pragma unroll
    for (int mt = 0; mt < 4; mt++)
        #pragma unroll
        for (int nt = 0; nt < 8; nt++)
            #pragma unroll
            for (int u = 0; u < 4; u++) acc[mt][nt][u] = 0.f;

    int j = lane >> 3;
    int lrow = lane & 7;
    int a_row_off = ((j & 1) << 3) + lrow;
    int a_byte_off = (j >> 1) << 4;
    int b_row_off = ((j >> 1) << 3) + lrow;
    int b_byte_off = (j & 1) << 4;

    #pragma unroll
    for (int p = 0; p < S - 1; p++) { load_stage(p, p); CPC(); }

    for (int k = 0; k < nk; k++) {
        CPW(S - 2);
        __syncthreads();
        if (k + S - 1 < nk) load_stage((k + S - 1) % S, k + S - 1);
        CPC();

        uint32_t a_s = sbase + (uint32_t)(k % S) * STAGE;
        uint32_t b_s = a_s + 16384u;
        #pragma unroll
        for (int ks = 0; ks < 4; ks++) {
            uint32_t af[4][4], bf[4][4];
            #pragma unroll
            for (int mt = 0; mt < 4; mt++) {
                int row = warp_m * 64 + mt * 16 + a_row_off;
                uint32_t ad = a_s + SWZ(row * 128 + ks * 32 + a_byte_off);
                LDM_X4(af[mt][0], af[mt][1], af[mt][2], af[mt][3], ad);
            }
            #pragma unroll
            for (int ng = 0; ng < 4; ng++) {
                int row = warp_n * 64 + ng * 16 + b_row_off;
                uint32_t bd = b_s + SWZ(row * 128 + ks * 32 + b_byte_off);
                LDM_X4(bf[ng][0], bf[ng][1], bf[ng][2], bf[ng][3], bd);
            }
            #pragma unroll
            for (int mt = 0; mt < 4; mt++)
                #pragma unroll
                for (int nt = 0; nt < 8; nt++) {
                    uint32_t b0 = bf[nt >> 1][(nt & 1) ? 2 : 0];
                    uint32_t b1 = bf[nt >> 1][(nt & 1) ? 3 : 1];
                    MMA_F16(acc[mt][nt], af[mt], b0, b1);
                }
        }
    }

    // ---------------- epilogue ----------------
    int gid = lane >> 2;
    int tig = lane & 3;
    #pragma unroll
    for (int mt = 0; mt < 4; mt++) {
        int m0 = bm + warp_m * 64 + mt * 16 + gid;
        #pragma unroll
        for (int nt = 0; nt < 8; nt++) {
            int n0 = bn + warp_n * 64 + nt * 8 + tig * 2;
            float* ac = acc[mt][nt];
            #pragma unroll
            for (int half_ = 0; half_ < 2; half_++) {
                int m = m0 + half_ * 8;
                float v0 = ac[half_ * 2], v1 = ac[half_ * 2 + 1];
                if (EPI == 1) {
                    float z0 = v0 + bias[n0], z1 = v1 + bias[n0 + 1];
                    float2 w;
                    w.x = z0 / (1.f + expf(-z0));
                    w.y = z1 / (1.f + expf(-z1));
                    *(float2*)&Cout[(size_t)m * N + n0] = w;
                } else if (EPI == 2) {
                    float2 w; w.x = v0; w.y = v1;
                    *(float2*)&Cout[(size_t)m * N + n0] = w;
                } else if (EPI == 3) {
                    size_t o = (size_t)m * N + n0;
                    float2 w;
                    w.x = v0 + bias[n0]     + aux0[o]     + aux1[o];
                    w.y = v1 + bias[n0 + 1] + aux0[o + 1] + aux1[o + 1];
                    *(float2*)&Cout[o] = w;
                } else if (EPI == 4) {  // gelu -> fp16
                    float g0 = 0.5f * v0 * (1.0f + erff(v0 * 0.70710678118654752f));
                    float g1 = 0.5f * v1 * (1.0f + erff(v1 * 0.70710678118654752f));
                    *(__half2*)(osplit + (size_t)m * N + n0) =
                        __halves2half2(__float2half(g0), __float2half(g1));
                } else {  // EPI 5: merged qkvff
                    if (n0 < C3) {
                        float w0 = v0, w1 = v1;
                        if (n0 < 2048) {
                            const float4* rot = (const float4*)aux0;
                            float4 rt = rot[((size_t)(m & (T_ - 1)) << 9) + ((n0 & 1023) >> 1)];
                            float cc = (n0 < 1024) ? rt.x : rt.z;
                            float ss = (n0 < 1024) ? rt.y : rt.w;
                            w0 = v0 * cc - v1 * ss;
                            w1 = v1 * cc + v0 * ss;
                        }
                        *(__half2*)(osplit + (size_t)m * C3 + n0) =
                            __halves2half2(__float2half(w0), __float2half(w1));
                    } else {
                        float g0 = 0.5f * v0 * (1.0f + erff(v0 * 0.70710678118654752f));
                        float g1 = 0.5f * v1 * (1.0f + erff(v1 * 0.70710678118654752f));
                        __half* ffp = (__half*)aux1;
                        *(__half2*)(ffp + (size_t)m * 2048 + (n0 - C3)) =
                            __halves2half2(__float2half(g0), __float2half(g1));
                    }
                }
            }
        }
    }
}

// ---------------- flat fp32 -> fp16 convert ----------------
__global__ void k_half1(const float4* __restrict__ in, __half* __restrict__ out) {
    int idx = blockIdx.x * 256 + threadIdx.x;
    float4 v = in[idx];
    uint2 hp;
    ((__half2*)&hp)[0] = __halves2half2(__float2half(v.x), __float2half(v.y));
    ((__half2*)&hp)[1] = __halves2half2(__float2half(v.z), __float2half(v.w));
    *(uint2*)(out + (size_t)idx * 4) = hp;
}

// ---------------- rotary table ----------------
__global__ void k_rotab() {
    int idx = blockIdx.x * 256 + threadIdx.x;        // over T_*512
    int t = idx >> 9;
    int j = idx & 511;
    float invf  = powf(10000.0f, -(float)j / 512.0f);
    float theta = (float)t * invf;
    float sn, cs;
    sincosf(theta, &sn, &cs);
    float svec  = (2.0f * (float)j + 0.4f * 1024.0f) / (1.4f * 1024.0f);
    float pw    = ((float)t - 1024.0f) * (1.0f / 512.0f);
    float scale = powf(svec, pw);
    float4 r;
    r.x = cs * scale;  r.y = sn * scale;
    r.z = cs / scale;  r.w = sn / scale;
    g_rot[idx] = r;
}

// ---------------- K1: RMSNorm -> a_q1 fp16, plus raw-x fp16 ----------------
__global__ void k_rmsnorm(const float* __restrict__ x, const float* __restrict__ rms_w) {
    int n = blockIdx.x;
    const float* xr = x + (size_t)n * C_;
    __shared__ float red[256];
    float s = 0.f;
    for (int c = threadIdx.x; c < C_; c += 256) { float v = xr[c]; s += v * v; }
    red[threadIdx.x] = s; __syncthreads();
    for (int o = 128; o > 0; o >>= 1) {
        if (threadIdx.x < o) red[threadIdx.x] += red[threadIdx.x + o];
        __syncthreads();
    }
    float nrm = sqrtf(red[0]) * 0.03125f;
    float inv = 1.0f / fmaxf(nrm, 1e-8f);
    for (int c = threadIdx.x; c < C_; c += 256) {
        float xv = xr[c];
        g_a_q1[(size_t)n * C_ + c] = __float2half(xv * inv * rms_w[c]);
        g_a_x1[(size_t)n * C_ + c] = __float2half(xv);
    }
}

// ---------------- K4: chunk KV summaries via tensor cores ----------------
__global__ void __launch_bounds__(256) k_chunk_kv() {
    __shared__ __align__(16) __half Kd[64 * 72], Vt[64 * 72];
    __shared__ float dec[64];
    int blk = blockIdx.x;
    int bh = blk / NC, c = blk % NC;
    int b = bh / H_, h = bh % H_;
    float gamma = 1.0f - exp2f(-5.0f - (float)h);
    if (threadIdx.x < 64) dec[threadIdx.x] = powf(gamma, (float)(HD - threadIdx.x));
    __syncthreads();
    for (int i = threadIdx.x; i < 4096; i += 256) {
        int j = i >> 6, d = i & 63;
        size_t base = (size_t)(b * T_ + c * HD + j) * C3 + h * HD + d;
        Kd[j * 72 + d] = __float2half(__half2float(g_qkv16[base + C_]) * dec[j]);
        Vt[j * 72 + d] = g_qkv16[base + 2 * C_];
    }
    __syncthreads();
    int wid = threadIdx.x >> 5, lane = threadIdx.x & 31;
    int m0 = (wid & 3) << 4, n0 = (wid >> 2) << 5;
    int jj = lane >> 3, lrow = lane & 7;
    int off1_row = ((jj & 1) << 3) + lrow, off1_byte = (jj >> 1) << 4;
    int off2_row = ((jj >> 1) << 3) + lrow, off2_byte = (jj & 1) << 4;
    uint32_t sK = smem_u32(Kd), sV = smem_u32(Vt);
    const int RS = 144;
    float acc[4][4];
    #pragma unroll
    for (int nt = 0; nt < 4; nt++)
        #pragma unroll
        for (int u = 0; u < 4; u++) acc[nt][u] = 0.f;
    #pragma unroll
    for (int ks = 0; ks < 4; ks++) {
        uint32_t af[4];
        LDM_X4T(af[0], af[1], af[2], af[3],
                sK + (ks * 16 + off2_row) * RS + m0 * 2 + off2_byte);
        #pragma unroll
        for (int nb = 0; nb < 2; nb++) {
            uint32_t bf[4];
            LDM_X4T(bf[0], bf[1], bf[2], bf[3],
                    sV + (ks * 16 + off1_row) * RS + (n0 + nb * 16) * 2 + off1_byte);
            MMA_F16(acc[nb * 2],     af, bf[0], bf[1]);
            MMA_F16(acc[nb * 2 + 1], af, bf[2], bf[3]);
        }
    }
    int gid = lane >> 2, tig = lane & 3;
    float* Wout = g_W + ((size_t)bh * NC + c) * 4096;
    #pragma unroll
    for (int nt = 0; nt < 4; nt++) {
        int e = n0 + nt * 8 + tig * 2;
        #pragma unroll
        for (int hf = 0; hf < 2; hf++) {
            int d = m0 + gid + hf * 8;
            float2 w; w.x = acc[nt][hf * 2]; w.y = acc[nt][hf * 2 + 1];
            *(float2*)&Wout[d * 64 + e] = w;
        }
    }
}

// ---------------- K5: state scan (fp32 state, fp16 output) ----------------
__global__ void k_scan() {
    int blk = blockIdx.x;            // BH*4
    int bh = blk >> 2, part = blk & 3;
    int h = bh % H_;
    float gamma = 1.0f - exp2f(-5.0f - (float)h);
    float g64 = powf(gamma, 64.0f);
    int i = part * 1024 + threadIdx.x * 4;
    float4 st; st.x = st.y = st.z = st.w = 0.f;
    size_t base0 = (size_t)bh * NC * 4096 + i;
    for (int c = 0; c < NC; c++) {
        size_t base = base0 + (size_t)c * 4096;
        uint2 hp;
        ((__half2*)&hp)[0] = __halves2half2(__float2half(st.x), __float2half(st.y));
        ((__half2*)&hp)[1] = __halves2half2(__float2half(st.z), __float2half(st.w));
        *(uint2*)&g_S16[base] = hp;
        float4 w = *(const float4*)&g_W[base];
        st.x = st.x * g64 + w.x;
        st.y = st.y * g64 + w.y;
        st.z = st.z * g64 + w.z;
        st.w = st.w * g64 + w.w;
    }
}

// ---------------- K6: tensor-core chunk attention + fused GN + gate ----------------
__global__ void __launch_bounds__(256) k_chunk_attn(
    const float* __restrict__ gn_w, const float* __restrict__ gn_b) {
    extern __shared__ __align__(16) char smraw[];
    __half* Qs = (__half*)smraw;           // 64*72
    __half* Ks = Qs + 64 * 72;
    __half* Vs = Ks + 64 * 72;
    __half* Ss = Vs + 64 * 72;
    __half* Am = Ss + 64 * 72;
    float* gpow = (float*)(Am + 64 * 72);  // 64
    float* Yb = (float*)smraw;             // aliases Qs+Ks

    int blk = blockIdx.x;
    int bh = blk / NC, c = blk % NC;
    int b = bh / H_, h = bh % H_;
    float gamma = 1.0f - exp2f(-5.0f - (float)h);
    if (threadIdx.x < 64) gpow[threadIdx.x] = powf(gamma, (float)threadIdx.x);
    for (int i = threadIdx.x; i < 4096; i += 256) {
        int j = i >> 6, d = i & 63;
        size_t base = (size_t)(b * T_ + c * HD + j) * C3 + h * HD + d;
        Qs[j * 72 + d] = g_qkv16[base];
        Ks[j * 72 + d] = g_qkv16[base + C_];
        Vs[j * 72 + d] = g_qkv16[base + 2 * C_];
        Ss[j * 72 + d] = g_S16[((size_t)bh * NC + c) * 4096 + i];
    }
    __syncthreads();
    int wid = threadIdx.x >> 5, lane = threadIdx.x & 31;
    int m0 = (wid & 3) << 4, n0 = (wid >> 2) << 5;
    int jj = lane >> 3, lrow = lane & 7;
    int off1_row = ((jj & 1) << 3) + lrow, off1_byte = (jj >> 1) << 4;
    int off2_row = ((jj >> 1) << 3) + lrow, off2_byte = (jj & 1) << 4;
    uint32_t sQ = smem_u32(Qs), sK = smem_u32(Ks), sV = smem_u32(Vs);
    uint32_t sS = smem_u32(Ss), sA = smem_u32(Am);
    const int RS = 144;
    int gid = lane >> 2, tig = lane & 3;

    // ---- phase 1: scores = Q K^T, mask+decay -> Am fp16 ----
    {
        float acc[4][4];
        #pragma unroll
        for (int nt = 0; nt < 4; nt++)
            #pragma unroll
            for (int u = 0; u < 4; u++) acc[nt][u] = 0.f;
        #pragma unroll
        for (int ks = 0; ks < 4; ks++) {
            uint32_t af[4];
            LDM_X4(af[0], af[1], af[2], af[3],
                   sQ + (m0 + off1_row) * RS + ks * 32 + off1_byte);
            #pragma unroll
            for (int nb = 0; nb < 2; nb++) {
                uint32_t bf[4];
                LDM_X4(bf[0], bf[1], bf[2], bf[3],
                       sK + (n0 + nb * 16 + off2_row) * RS + ks * 32 + off2_byte);
                MMA_F16(acc[nb * 2],     af, bf[0], bf[1]);
                MMA_F16(acc[nb * 2 + 1], af, bf[2], bf[3]);
            }
        }
        #pragma unroll
        for (int nt = 0; nt < 4; nt++) {
            int n = n0 + nt * 8 + tig * 2;
            #pragma unroll
            for (int hf = 0; hf < 2; hf++) {
                int i = m0 + gid + hf * 8;
                float v0 = acc[nt][hf * 2], v1 = acc[nt][hf * 2 + 1];
                v0 = (n     <= i) ? v0 * gpow[i - n]     : 0.f;
                v1 = (n + 1 <= i) ? v1 * gpow[i - n - 1] : 0.f;
                *(__half2*)(Am + i * 72 + n) =
                    __halves2half2(__float2half(v0), __float2half(v1));
            }
        }
    }
    __syncthreads();
    // ---- phase 2: Y = Am V + gpow[i] * Q S ----
    float a2[4][4], a3[4][4];
    #pragma unroll
    for (int nt = 0; nt < 4; nt++)
        #pragma unroll
        for (int u = 0; u < 4; u++) { a2[nt][u] = 0.f; a3[nt][u] = 0.f; }
    #pragma unroll
    for (int ks = 0; ks < 4; ks++) {
        uint32_t afA[4], afQ[4];
        LDM_X4(afA[0], afA[1], afA[2], afA[3],
               sA + (m0 + off1_row) * RS + ks * 32 + off1_byte);
        LDM_X4(afQ[0], afQ[1], afQ[2], afQ[3],
               sQ + (m0 + off1_row) * RS + ks * 32 + off1_byte);
        #pragma unroll
        for (int nb = 0; nb < 2; nb++) {
            uint32_t bv[4], bs[4];
            LDM_X4T(bv[0], bv[1], bv[2], bv[3],
                    sV + (ks * 16 + off1_row) * RS + (n0 + nb * 16) * 2 + off1_byte);
            LDM_X4T(bs[0], bs[1], bs[2], bs[3],
                    sS + (ks * 16 + off1_row) * RS + (n0 + nb * 16) * 2 + off1_byte);
            MMA_F16(a2[nb * 2],     afA, bv[0], bv[1]);
            MMA_F16(a2[nb * 2 + 1], afA, bv[2], bv[3]);
            MMA_F16(a3[nb * 2],     afQ, bs[0], bs[1]);
            MMA_F16(a3[nb * 2 + 1], afQ, bs[2], bs[3]);
        }
    }
    __syncthreads();
    #pragma unroll
    for (int nt = 0; nt < 4; nt++) {
        int n = n0 + nt * 8 + tig * 2;
        #pragma unroll
        for (int hf = 0; hf < 2; hf++) {
            int i = m0 + gid + hf * 8;
            float gi = gpow[i];
            Yb[i * 68 + n]     = (a2[nt][hf * 2]     + gi * a3[nt][hf * 2])     * 0.125f;
            Yb[i * 68 + n + 1] = (a2[nt][hf * 2 + 1] + gi * a3[nt][hf * 2 + 1]) * 0.125f;
        }
    }
    __syncthreads();
    // ---- GN + gate -> a_prj1 fp16 ----
    int i = threadIdx.x >> 2;
    int e0 = (threadIdx.x & 3) << 4;
    float vv[16];
    float sum = 0.f, sq = 0.f;
    #pragma unroll
    for (int u = 0; u < 16; u++) {
        float v = Yb[i * 68 + e0 + u];
        vv[u] = v; sum += v; sq += v * v;
    }
    sum += __shfl_xor_sync(~0u, sum, 1); sq += __shfl_xor_sync(~0u, sq, 1);
    sum += __shfl_xor_sync(~0u, sum, 2); sq += __shfl_xor_sync(~0u, sq, 2);
    float mu  = sum * (1.0f / 64.0f);
    float var = sq * (1.0f / 64.0f) - mu * mu;
    float inv = rsqrtf(var + 1e-5f);
    size_t row = (size_t)(b * T_ + c * HD + i);
    int cb = h * 64 + e0;
    #pragma unroll
    for (int u = 0; u < 16; u += 4) {
        float4 gw = *(const float4*)&gn_w[cb + u];
        float4 gb = *(const float4*)&gn_b[cb + u];
        float4 zv = *(const float4*)&g_z[row * C_ + cb + u];
        float o0 = ((vv[u]     - mu) * inv * gw.x + gb.x) * zv.x;
        float o1 = ((vv[u + 1] - mu) * inv * gw.y + gb.y) * zv.y;
        float o2 = ((vv[u + 2] - mu) * inv * gw.z + gb.z) * zv.z;
        float o3 = ((vv[u + 3] - mu) * inv * gw.w + gb.w) * zv.w;
        uint2 hp;
        ((__half2*)&hp)[0] = __halves2half2(__float2half(o0), __float2half(o1));
        ((__half2*)&hp)[1] = __halves2half2(__float2half(o2), __float2half(o3));
        *(uint2*)(g_a_prj1 + row * C_ + cb + u) = hp;
    }
}

// ---------------- launch ----------------
extern "C" void kernel_launch(void* const* d_in, const int* in_sizes, int n_in,
                              void* d_out, int out_size) {
    const float* x       = (const float*)d_in[0];
    const float* w_qkvff = (const float*)d_in[1];
    const float* w_gated = (const float*)d_in[2];
    const float* b_gated = (const float*)d_in[3];
    const float* w_proj  = (const float*)d_in[4];
    const float* b_proj  = (const float*)d_in[5];
    const float* gn_w    = (const float*)d_in[6];
    const float* gn_b    = (const float*)d_in[7];
    const float* w_ff    = (const float*)d_in[8];
    const float* rms_w   = (const float*)d_in[9];
    float* out = (float*)d_out;

    float *p_z, *p_ffout;
    float4* p_rot;
    __half *p_qkv16, *p_a_q1, *p_b_qkv1, *p_a_x1, *p_b_gat1, *p_a_prj1, *p_b_prj1, *p_a_ff1, *p_b_ff1;
    cudaGetSymbolAddress((void**)&p_qkv16, g_qkv16);
    cudaGetSymbolAddress((void**)&p_z,     g_z);
    cudaGetSymbolAddress((void**)&p_ffout, g_ffout);
    cudaGetSymbolAddress((void**)&p_rot,   g_rot);
    cudaGetSymbolAddress((void**)&p_a_q1,  g_a_q1);
    cudaGetSymbolAddress((void**)&p_b_qkv1, g_b_qkv1);
    cudaGetSymbolAddress((void**)&p_a_x1,  g_a_x1);
    cudaGetSymbolAddress((void**)&p_b_gat1, g_b_gat1);
    cudaGetSymbolAddress((void**)&p_a_prj1, g_a_prj1);
    cudaGetSymbolAddress((void**)&p_b_prj1, g_b_prj1);
    cudaGetSymbolAddress((void**)&p_a_ff1, g_a_ff1);
    cudaGetSymbolAddress((void**)&p_b_ff1, g_b_ff1);

    const int SMEM = 1024 + 4 * 49152;               // 197632
    const int ATTN_SMEM = 5 * 64 * 72 * 2 + 256;     // 46336

    static cudaStream_t s1 = nullptr;
    static cudaEvent_t ev0, ev_ax, ev_wq, ev_qkv, ev_gate, ev_ff;
    if (s1 == nullptr) {
        cudaStreamCreateWithFlags(&s1, cudaStreamNonBlocking);
        cudaEventCreateWithFlags(&ev0,     cudaEventDisableTiming);
        cudaEventCreateWithFlags(&ev_ax,   cudaEventDisableTiming);
        cudaEventCreateWithFlags(&ev_wq,   cudaEventDisableTiming);
        cudaEventCreateWithFlags(&ev_qkv,  cudaEventDisableTiming);
        cudaEventCreateWithFlags(&ev_gate, cudaEventDisableTiming);
        cudaEventCreateWithFlags(&ev_ff,   cudaEventDisableTiming);
        cudaFuncSetAttribute(mma_gemm<1>, cudaFuncAttributeMaxDynamicSharedMemorySize, SMEM);
        cudaFuncSetAttribute(mma_gemm<2>, cudaFuncAttributeMaxDynamicSharedMemorySize, SMEM);
        cudaFuncSetAttribute(mma_gemm<3>, cudaFuncAttributeMaxDynamicSharedMemorySize, SMEM);
        cudaFuncSetAttribute(mma_gemm<5>, cudaFuncAttributeMaxDynamicSharedMemorySize, SMEM);
        cudaFuncSetAttribute(k_chunk_attn, cudaFuncAttributeMaxDynamicSharedMemorySize, ATTN_SMEM);
    }

    // ---- fork ----
    cudaEventRecord(ev0, 0);
    cudaStreamWaitEvent(s1, ev0, 0);

    // s1: all weight converts (qkvff first; main waits on it before the big GEMM)
    k_half1<<<(C5 * C_) / 1024, 256, 0, s1>>>((const float4*)w_qkvff, p_b_qkv1);
    cudaEventRecord(ev_wq, s1);
    k_half1<<<(C_ * C_) / 1024, 256, 0, s1>>>((const float4*)w_gated, p_b_gat1);
    k_half1<<<(C_ * C_) / 1024, 256, 0, s1>>>((const float4*)w_proj,  p_b_prj1);
    k_half1<<<(C_ * 2 * C_) / 1024, 256, 0, s1>>>((const float4*)w_ff, p_b_ff1);

    // main: rotary table + RMSNorm (concurrent with s1 converts)
    k_rotab<<<(T_ * 512) / 256, 256>>>();
    k_rmsnorm<<<BT, 256>>>(x, rms_w);
    cudaEventRecord(ev_ax, 0);

    // s1: gate GEMM z = silu(x @ w_gated^T + b)
    cudaStreamWaitEvent(s1, ev_ax, 0);
    mma_gemm<1><<<dim3(C_ / 256, BT / 128), 256, SMEM, s1>>>(
        p_a_x1, p_b_gat1, C_, C_, p_z, b_gated, nullptr, nullptr, nullptr);
    cudaEventRecord(ev_gate, s1);

    // main: merged qkvff GEMM (N=5120): rotary qkv -> g_qkv16, gelu ff -> a_ff1
    cudaStreamWaitEvent(0, ev_wq, 0);
    mma_gemm<5><<<dim3(C5 / 256, BT / 128), 256, SMEM>>>(
        p_a_q1, p_b_qkv1, C_, C5, nullptr, nullptr,
        (const float*)p_rot, (const float*)p_a_ff1, p_qkv16);
    cudaEventRecord(ev_qkv, 0);

    // s1: ff GEMM ffout = gelu(ff) @ w_ff^T  (needs a_ff1)
    cudaStreamWaitEvent(s1, ev_qkv, 0);
    mma_gemm<2><<<dim3(C_ / 256, BT / 128), 256, SMEM, s1>>>(
        p_a_ff1, p_b_ff1, 2 * C_, C_, p_ffout, nullptr, nullptr, nullptr, nullptr);
    cudaEventRecord(ev_ff, s1);

    // main: tensor-core attention chain (overlaps s1's ff GEMM)
    k_chunk_kv<<<BH * NC, 256>>>();
    k_scan<<<BH * 4, 256>>>();
    cudaStreamWaitEvent(0, ev_gate, 0);
    k_chunk_attn<<<BH * NC, 256, ATTN_SMEM>>>(gn_w, gn_b);

    // join ff, then final proj GEMM: out = y2 @ w_proj^T + b_proj + x + ffout
    cudaStreamWaitEvent(0, ev_ff, 0);
    mma_gemm<3><<<dim3(C_ / 256, BT / 128), 256, SMEM>>>(
        p_a_prj1, p_b_prj1, C_, C_, out, b_proj, x, p_ffout, nullptr);
}

// round 15
// speedup vs baseline: 1.0365x; 1.0365x over previous
#include <cuda_runtime.h>
#include <cuda_fp16.h>
#include <math.h>
#include <stdint.h>

#define B_  2
#define T_  2048
#define C_  1024
#define H_  16
#define HD  64
#define BT  (B_*T_)      // 4096
#define C3  (3*C_)       // 3072
#define C5  (5*C_)       // 5120
#define NC  (T_/HD)      // 32 chunks
#define BH  (B_*H_)      // 32

// ---------------- scratch (device globals) ----------------
__device__ __half g_qkv16[BT*(size_t)C3];         // q,k,v fp16 (stride 3C), rotary applied
__device__ float  g_W [BH*(size_t)NC*HD*HD];
__device__ __half g_S16[BH*(size_t)NC*HD*HD];     // scanned states fp16
__device__ float  g_z [BT*(size_t)C_];            // silu(gate) fp32
__device__ float  g_ffout[BT*(size_t)C_];         // ff GEMM result
__device__ float4 g_rot [T_*(size_t)512];         // (cq,sq,ck,sk) per (t,j)
// single fp16 operands
__device__ __half g_a_q1  [BT*(size_t)C_];        // rms-normed x
__device__ __half g_b_qkv1[C5*(size_t)C_];
__device__ __half g_a_x1  [BT*(size_t)C_];        // raw x
__device__ __half g_b_gat1[C_*(size_t)C_];
__device__ __half g_a_prj1[BT*(size_t)C_];
__device__ __half g_b_prj1[C_*(size_t)C_];
__device__ __half g_a_ff1 [BT*(size_t)2*C_];      // gelu(ff) fp16
__device__ __half g_b_ff1 [C_*(size_t)2*C_];

// ---------------- PTX helpers ----------------
__device__ __forceinline__ uint32_t smem_u32(const void* p) {
    uint32_t a;
    asm("{ .reg .u64 t; cvta.to.shared.u64 t, %1; cvt.u32.u64 %0, t; }" : "=r"(a) : "l"(p));
    return a;
}
#define CPA(dst, src)  asm volatile("cp.async.cg.shared.global [%0], [%1], 16;" :: "r"(dst), "l"(src) : "memory")
#define CPC()          asm volatile("cp.async.commit_group;" ::: "memory")
#define CPW(n)         asm volatile("cp.async.wait_group %0;" :: "n"(n) : "memory")
#define SWZ(o) ((o) ^ (((o) >> 3) & 0x70))

#define LDM_X4(r0, r1, r2, r3, a) \
    asm volatile("ldmatrix.sync.aligned.m8n8.x4.shared.b16 {%0,%1,%2,%3}, [%4];" \
        : "=r"(r0), "=r"(r1), "=r"(r2), "=r"(r3) : "r"(a))
#define LDM_X4T(r0, r1, r2, r3, a) \
    asm volatile("ldmatrix.sync.aligned.m8n8.x4.trans.shared.b16 {%0,%1,%2,%3}, [%4];" \
        : "=r"(r0), "=r"(r1), "=r"(r2), "=r"(r3) : "r"(a))

#define MMA_F16(d, a, b0, b1) \
    asm volatile("mma.sync.aligned.m16n8k16.row.col.f32.f16.f16.f32 " \
        "{%0,%1,%2,%3}, {%4,%5,%6,%7}, {%8,%9}, {%0,%1,%2,%3};" \
        : "+f"((d)[0]), "+f"((d)[1]), "+f"((d)[2]), "+f"((d)[3]) \
        : "r"((a)[0]), "r"((a)[1]), "r"((a)[2]), "r"((a)[3]), "r"(b0), "r"(b1))

// ---------------- warp-MMA fp16 NT GEMM (proven R4 mainloop) ----------------
// EPI 1: silu(v+bias[n]) -> fp32 Cout
// EPI 2: plain -> Cout
// EPI 3: v + bias[n] + aux0[o] + aux1[o] -> Cout
// EPI 4: gelu(v) -> fp16 osplit (row stride N)
// EPI 5: qkv: fused xPos rotary (n<2048 via aux0 table) -> fp16 osplit (row stride N)
template<int EPI>
__global__ void __launch_bounds__(256, 1) mma_gemm(
    const __half* __restrict__ A, const __half* __restrict__ Bm,
    int Kp, int N, float* __restrict__ Cout,
    const float* __restrict__ bias, const float* __restrict__ aux0,
    const float* __restrict__ aux1, __half* __restrict__ osplit)
{
    extern __shared__ __align__(1024) char smem_raw[];
    const int S = 4;
    const uint32_t STAGE = 49152;   // A 16KB + B 32KB
    uint32_t sbase = (smem_u32(smem_raw) + 1023) & ~1023u;

    int tid = threadIdx.x;
    int wid = tid >> 5, lane = tid & 31;
    int warp_m = wid & 1, warp_n = wid >> 1;
    int bm = blockIdx.y << 7, bn = blockIdx.x << 8;

    const int nk = Kp >> 6;

    auto load_stage = [&](int s, int k) {
        uint32_t a_s = sbase + s * STAGE;
        uint32_t b_s = a_s + 16384u;
        const __half* Ag = A + (size_t)bm * Kp + (size_t)k * 64;
        const __half* Bg = Bm + (size_t)bn * Kp + (size_t)k * 64;
        #pragma unroll
        for (int q = 0; q < 4; q++) {
            int i = tid + (q << 8);
            int r = i >> 3, c = i & 7;
            uint32_t off = SWZ(r * 128 + c * 16);
            CPA(a_s + off, (const char*)(Ag + (size_t)r * Kp + c * 8));
        }
        #pragma unroll
        for (int q = 0; q < 8; q++) {
            int i = tid + (q << 8);
            int r = i >> 3, c = i & 7;
            uint32_t off = SWZ(r * 128 + c * 16);
            CPA(b_s + off, (const char*)(Bg + (size_t)r * Kp + c * 8));
        }
    };

    float acc[4][8][4];
    #pragma unroll
    for (int mt = 0; mt < 4; mt++)
        #pragma unroll
        for (int nt = 0; nt < 8; nt++)
            #pragma unroll
            for (int u = 0; u < 4; u++) acc[mt][nt][u] = 0.f;

    int j = lane >> 3;
    int lrow = lane & 7;
    int a_row_off = ((j & 1) << 3) + lrow;
    int a_byte_off = (j >> 1) << 4;
    int b_row_off = ((j >> 1) << 3) + lrow;
    int b_byte_off = (j & 1) << 4;

    #pragma unroll
    for (int p = 0; p < S - 1; p++) { load_stage(p, p); CPC(); }

    for (int k = 0; k < nk; k++) {
        CPW(S - 2);
        __syncthreads();
        if (k + S - 1 < nk) load_stage((k + S - 1) % S, k + S - 1);
        CPC();

        uint32_t a_s = sbase + (uint32_t)(k % S) * STAGE;
        uint32_t b_s = a_s + 16384u;
        #pragma unroll
        for (int ks = 0; ks < 4; ks++) {
            uint32_t af[4][4], bf[4][4];
            #pragma unroll
            for (int mt = 0; mt < 4; mt++) {
                int row = warp_m * 64 + mt * 16 + a_row_off;
                uint32_t ad = a_s + SWZ(row * 128 + ks * 32 + a_byte_off);
                LDM_X4(af[mt][0], af[mt][1], af[mt][2], af[mt][3], ad);
            }
            #pragma unroll
            for (int ng = 0; ng < 4; ng++) {
                int row = warp_n * 64 + ng * 16 + b_row_off;
                uint32_t bd = b_s + SWZ(row * 128 + ks * 32 + b_byte_off);
                LDM_X4(bf[ng][0], bf[ng][1], bf[ng][2], bf[ng][3], bd);
            }
            #pragma unroll
            for (int mt = 0; mt < 4; mt++)
                #pragma unroll
                for (int nt = 0; nt < 8; nt++) {
                    uint32_t b0 = bf[nt >> 1][(nt & 1) ? 2 : 0];
                    uint32_t b1 = bf[nt >> 1][(nt & 1) ? 3 : 1];
                    MMA_F16(acc[mt][nt], af[mt], b0, b1);
                }
        }
    }

    // ---------------- epilogue ----------------
    int gid = lane >> 2;
    int tig = lane & 3;
    #pragma unroll
    for (int mt = 0; mt < 4; mt++) {
        int m0 = bm + warp_m * 64 + mt * 16 + gid;
        #pragma unroll
        for (int nt = 0; nt < 8; nt++) {
            int n0 = bn + warp_n * 64 + nt * 8 + tig * 2;
            float* ac = acc[mt][nt];
            #pragma unroll
            for (int half_ = 0; half_ < 2; half_++) {
                int m = m0 + half_ * 8;
                float v0 = ac[half_ * 2], v1 = ac[half_ * 2 + 1];
                if (EPI == 1) {
                    float z0 = v0 + bias[n0], z1 = v1 + bias[n0 + 1];
                    float2 w;
                    w.x = z0 / (1.f + expf(-z0));
                    w.y = z1 / (1.f + expf(-z1));
                    *(float2*)&Cout[(size_t)m * N + n0] = w;
                } else if (EPI == 2) {
                    float2 w; w.x = v0; w.y = v1;
                    *(float2*)&Cout[(size_t)m * N + n0] = w;
                } else if (EPI == 3) {
                    size_t o = (size_t)m * N + n0;
                    float2 w;
                    w.x = v0 + bias[n0]     + aux0[o]     + aux1[o];
                    w.y = v1 + bias[n0 + 1] + aux0[o + 1] + aux1[o + 1];
                    *(float2*)&Cout[o] = w;
                } else if (EPI == 4) {  // gelu -> fp16
                    float g0 = 0.5f * v0 * (1.0f + erff(v0 * 0.70710678118654752f));
                    float g1 = 0.5f * v1 * (1.0f + erff(v1 * 0.70710678118654752f));
                    *(__half2*)(osplit + (size_t)m * N + n0) =
                        __halves2half2(__float2half(g0), __float2half(g1));
                } else {  // EPI 5: fused xPos rotary -> fp16
                    float w0 = v0, w1 = v1;
                    if (n0 < 2048) {
                        const float4* rot = (const float4*)aux0;
                        float4 rt = rot[((size_t)(m & (T_ - 1)) << 9) + ((n0 & 1023) >> 1)];
                        float cc = (n0 < 1024) ? rt.x : rt.z;
                        float ss = (n0 < 1024) ? rt.y : rt.w;
                        w0 = v0 * cc - v1 * ss;
                        w1 = v1 * cc + v0 * ss;
                    }
                    *(__half2*)(osplit + (size_t)m * N + n0) =
                        __halves2half2(__float2half(w0), __float2half(w1));
                }
            }
        }
    }
}

// ---------------- flat fp32 -> fp16 convert ----------------
__global__ void k_half1(const float4* __restrict__ in, __half* __restrict__ out) {
    int idx = blockIdx.x * 256 + threadIdx.x;
    float4 v = in[idx];
    uint2 hp;
    ((__half2*)&hp)[0] = __halves2half2(__float2half(v.x), __float2half(v.y));
    ((__half2*)&hp)[1] = __halves2half2(__float2half(v.z), __float2half(v.w));
    *(uint2*)(out + (size_t)idx * 4) = hp;
}

// ---------------- rotary table ----------------
__global__ void k_rotab() {
    int idx = blockIdx.x * 256 + threadIdx.x;        // over T_*512
    int t = idx >> 9;
    int j = idx & 511;
    float invf  = powf(10000.0f, -(float)j / 512.0f);
    float theta = (float)t * invf;
    float sn, cs;
    sincosf(theta, &sn, &cs);
    float svec  = (2.0f * (float)j + 0.4f * 1024.0f) / (1.4f * 1024.0f);
    float pw    = ((float)t - 1024.0f) * (1.0f / 512.0f);
    float scale = powf(svec, pw);
    float4 r;
    r.x = cs * scale;  r.y = sn * scale;
    r.z = cs / scale;  r.w = sn / scale;
    g_rot[idx] = r;
}

// ---------------- K1: RMSNorm -> a_q1 fp16, plus raw-x fp16 ----------------
__global__ void k_rmsnorm(const float* __restrict__ x, const float* __restrict__ rms_w) {
    int n = blockIdx.x;
    const float* xr = x + (size_t)n * C_;
    __shared__ float red[256];
    float s = 0.f;
    for (int c = threadIdx.x; c < C_; c += 256) { float v = xr[c]; s += v * v; }
    red[threadIdx.x] = s; __syncthreads();
    for (int o = 128; o > 0; o >>= 1) {
        if (threadIdx.x < o) red[threadIdx.x] += red[threadIdx.x + o];
        __syncthreads();
    }
    float nrm = sqrtf(red[0]) * 0.03125f;
    float inv = 1.0f / fmaxf(nrm, 1e-8f);
    for (int c = threadIdx.x; c < C_; c += 256) {
        float xv = xr[c];
        g_a_q1[(size_t)n * C_ + c] = __float2half(xv * inv * rms_w[c]);
        g_a_x1[(size_t)n * C_ + c] = __float2half(xv);
    }
}

// ---------------- K4: chunk KV summaries via tensor cores ----------------
__global__ void __launch_bounds__(256) k_chunk_kv() {
    __shared__ __align__(16) __half Kd[64 * 72], Vt[64 * 72];
    __shared__ float dec[64];
    int blk = blockIdx.x;
    int bh = blk / NC, c = blk % NC;
    int b = bh / H_, h = bh % H_;
    float gamma = 1.0f - exp2f(-5.0f - (float)h);
    if (threadIdx.x < 64) dec[threadIdx.x] = powf(gamma, (float)(HD - threadIdx.x));
    __syncthreads();
    for (int i = threadIdx.x; i < 4096; i += 256) {
        int j = i >> 6, d = i & 63;
        size_t base = (size_t)(b * T_ + c * HD + j) * C3 + h * HD + d;
        Kd[j * 72 + d] = __float2half(__half2float(g_qkv16[base + C_]) * dec[j]);
        Vt[j * 72 + d] = g_qkv16[base + 2 * C_];
    }
    __syncthreads();
    int wid = threadIdx.x >> 5, lane = threadIdx.x & 31;
    int m0 = (wid & 3) << 4, n0 = (wid >> 2) << 5;
    int jj = lane >> 3, lrow = lane & 7;
    int off1_row = ((jj & 1) << 3) + lrow, off1_byte = (jj >> 1) << 4;
    int off2_row = ((jj >> 1) << 3) + lrow, off2_byte = (jj & 1) << 4;
    uint32_t sK = smem_u32(Kd), sV = smem_u32(Vt);
    const int RS = 144;
    float acc[4][4];
    #pragma unroll
    for (int nt = 0; nt < 4; nt++)
        #pragma unroll
        for (int u = 0; u < 4; u++) acc[nt][u] = 0.f;
    #pragma unroll
    for (int ks = 0; ks < 4; ks++) {
        uint32_t af[4];
        LDM_X4T(af[0], af[1], af[2], af[3],
                sK + (ks * 16 + off2_row) * RS + m0 * 2 + off2_byte);
        #pragma unroll
        for (int nb = 0; nb < 2; nb++) {
            uint32_t bf[4];
            LDM_X4T(bf[0], bf[1], bf[2], bf[3],
                    sV + (ks * 16 + off1_row) * RS + (n0 + nb * 16) * 2 + off1_byte);
            MMA_F16(acc[nb * 2],     af, bf[0], bf[1]);
            MMA_F16(acc[nb * 2 + 1], af, bf[2], bf[3]);
        }
    }
    int gid = lane >> 2, tig = lane & 3;
    float* Wout = g_W + ((size_t)bh * NC + c) * 4096;
    #pragma unroll
    for (int nt = 0; nt < 4; nt++) {
        int e = n0 + nt * 8 + tig * 2;
        #pragma unroll
        for (int hf = 0; hf < 2; hf++) {
            int d = m0 + gid + hf * 8;
            float2 w; w.x = acc[nt][hf * 2]; w.y = acc[nt][hf * 2 + 1];
            *(float2*)&Wout[d * 64 + e] = w;
        }
    }
}

// ---------------- K5: state scan (fp32 state, fp16 output) ----------------
__global__ void k_scan() {
    int blk = blockIdx.x;            // BH*4
    int bh = blk >> 2, part = blk & 3;
    int h = bh % H_;
    float gamma = 1.0f - exp2f(-5.0f - (float)h);
    float g64 = powf(gamma, 64.0f);
    int i = part * 1024 + threadIdx.x * 4;
    float4 st; st.x = st.y = st.z = st.w = 0.f;
    size_t base0 = (size_t)bh * NC * 4096 + i;
    for (int c = 0; c < NC; c++) {
        size_t base = base0 + (size_t)c * 4096;
        uint2 hp;
        ((__half2*)&hp)[0] = __halves2half2(__float2half(st.x), __float2half(st.y));
        ((__half2*)&hp)[1] = __halves2half2(__float2half(st.z), __float2half(st.w));
        *(uint2*)&g_S16[base] = hp;
        float4 w = *(const float4*)&g_W[base];
        st.x = st.x * g64 + w.x;
        st.y = st.y * g64 + w.y;
        st.z = st.z * g64 + w.z;
        st.w = st.w * g64 + w.w;
    }
}

// ---------------- K6: tensor-core chunk attention + fused GN + gate ----------------
__global__ void __launch_bounds__(256) k_chunk_attn(
    const float* __restrict__ gn_w, const float* __restrict__ gn_b) {
    extern __shared__ __align__(16) char smraw[];
    __half* Qs = (__half*)smraw;           // 64*72
    __half* Ks = Qs + 64 * 72;
    __half* Vs = Ks + 64 * 72;
    __half* Ss = Vs + 64 * 72;
    __half* Am = Ss + 64 * 72;
    float* gpow = (float*)(Am + 64 * 72);  // 64
    float* Yb = (float*)smraw;             // aliases Qs+Ks

    int blk = blockIdx.x;
    int bh = blk / NC, c = blk % NC;
    int b = bh / H_, h = bh % H_;
    float gamma = 1.0f - exp2f(-5.0f - (float)h);
    if (threadIdx.x < 64) gpow[threadIdx.x] = powf(gamma, (float)threadIdx.x);
    for (int i = threadIdx.x; i < 4096; i += 256) {
        int j = i >> 6, d = i & 63;
        size_t base = (size_t)(b * T_ + c * HD + j) * C3 + h * HD + d;
        Qs[j * 72 + d] = g_qkv16[base];
        Ks[j * 72 + d] = g_qkv16[base + C_];
        Vs[j * 72 + d] = g_qkv16[base + 2 * C_];
        Ss[j * 72 + d] = g_S16[((size_t)bh * NC + c) * 4096 + i];
    }
    __syncthreads();
    int wid = threadIdx.x >> 5, lane = threadIdx.x & 31;
    int m0 = (wid & 3) << 4, n0 = (wid >> 2) << 5;
    int jj = lane >> 3, lrow = lane & 7;
    int off1_row = ((jj & 1) << 3) + lrow, off1_byte = (jj >> 1) << 4;
    int off2_row = ((jj >> 1) << 3) + lrow, off2_byte = (jj & 1) << 4;
    uint32_t sQ = smem_u32(Qs), sK = smem_u32(Ks), sV = smem_u32(Vs);
    uint32_t sS = smem_u32(Ss), sA = smem_u32(Am);
    const int RS = 144;
    int gid = lane >> 2, tig = lane & 3;

    // ---- phase 1: scores = Q K^T, mask+decay -> Am fp16 ----
    {
        float acc[4][4];
        #pragma unroll
        for (int nt = 0; nt < 4; nt++)
            #pragma unroll
            for (int u = 0; u < 4; u++) acc[nt][u] = 0.f;
        #pragma unroll
        for (int ks = 0; ks < 4; ks++) {
            uint32_t af[4];
            LDM_X4(af[0], af[1], af[2], af[3],
                   sQ + (m0 + off1_row) * RS + ks * 32 + off1_byte);
            #pragma unroll
            for (int nb = 0; nb < 2; nb++) {
                uint32_t bf[4];
                LDM_X4(bf[0], bf[1], bf[2], bf[3],
                       sK + (n0 + nb * 16 + off2_row) * RS + ks * 32 + off2_byte);
                MMA_F16(acc[nb * 2],     af, bf[0], bf[1]);
                MMA_F16(acc[nb * 2 + 1], af, bf[2], bf[3]);
            }
        }
        #pragma unroll
        for (int nt = 0; nt < 4; nt++) {
            int n = n0 + nt * 8 + tig * 2;
            #pragma unroll
            for (int hf = 0; hf < 2; hf++) {
                int i = m0 + gid + hf * 8;
                float v0 = acc[nt][hf * 2], v1 = acc[nt][hf * 2 + 1];
                v0 = (n     <= i) ? v0 * gpow[i - n]     : 0.f;
                v1 = (n + 1 <= i) ? v1 * gpow[i - n - 1] : 0.f;
                *(__half2*)(Am + i * 72 + n) =
                    __halves2half2(__float2half(v0), __float2half(v1));
            }
        }
    }
    __syncthreads();
    // ---- phase 2: Y = Am V + gpow[i] * Q S ----
    float a2[4][4], a3[4][4];
    #pragma unroll
    for (int nt = 0; nt < 4; nt++)
        #pragma unroll
        for (int u = 0; u < 4; u++) { a2[nt][u] = 0.f; a3[nt][u] = 0.f; }
    #pragma unroll
    for (int ks = 0; ks < 4; ks++) {
        uint32_t afA[4], afQ[4];
        LDM_X4(afA[0], afA[1], afA[2], afA[3],
               sA + (m0 + off1_row) * RS + ks * 32 + off1_byte);
        LDM_X4(afQ[0], afQ[1], afQ[2], afQ[3],
               sQ + (m0 + off1_row) * RS + ks * 32 + off1_byte);
        #pragma unroll
        for (int nb = 0; nb < 2; nb++) {
            uint32_t bv[4], bs[4];
            LDM_X4T(bv[0], bv[1], bv[2], bv[3],
                    sV + (ks * 16 + off1_row) * RS + (n0 + nb * 16) * 2 + off1_byte);
            LDM_X4T(bs[0], bs[1], bs[2], bs[3],
                    sS + (ks * 16 + off1_row) * RS + (n0 + nb * 16) * 2 + off1_byte);
            MMA_F16(a2[nb * 2],     afA, bv[0], bv[1]);
            MMA_F16(a2[nb * 2 + 1], afA, bv[2], bv[3]);
            MMA_F16(a3[nb * 2],     afQ, bs[0], bs[1]);
            MMA_F16(a3[nb * 2 + 1], afQ, bs[2], bs[3]);
        }
    }
    __syncthreads();
    #pragma unroll
    for (int nt = 0; nt < 4; nt++) {
        int n = n0 + nt * 8 + tig * 2;
        #pragma unroll
        for (int hf = 0; hf < 2; hf++) {
            int i = m0 + gid + hf * 8;
            float gi = gpow[i];
            Yb[i * 68 + n]     = (a2[nt][hf * 2]     + gi * a3[nt][hf * 2])     * 0.125f;
            Yb[i * 68 + n + 1] = (a2[nt][hf * 2 + 1] + gi * a3[nt][hf * 2 + 1]) * 0.125f;
        }
    }
    __syncthreads();
    // ---- GN + gate -> a_prj1 fp16 ----
    int i = threadIdx.x >> 2;
    int e0 = (threadIdx.x & 3) << 4;
    float vv[16];
    float sum = 0.f, sq = 0.f;
    #pragma unroll
    for (int u = 0; u < 16; u++) {
        float v = Yb[i * 68 + e0 + u];
        vv[u] = v; sum += v; sq += v * v;
    }
    sum += __shfl_xor_sync(~0u, sum, 1); sq += __shfl_xor_sync(~0u, sq, 1);
    sum += __shfl_xor_sync(~0u, sum, 2); sq += __shfl_xor_sync(~0u, sq, 2);
    float mu  = sum * (1.0f / 64.0f);
    float var = sq * (1.0f / 64.0f) - mu * mu;
    float inv = rsqrtf(var + 1e-5f);
    size_t row = (size_t)(b * T_ + c * HD + i);
    int cb = h * 64 + e0;
    #pragma unroll
    for (int u = 0; u < 16; u += 4) {
        float4 gw = *(const float4*)&gn_w[cb + u];
        float4 gb = *(const float4*)&gn_b[cb + u];
        float4 zv = *(const float4*)&g_z[row * C_ + cb + u];
        float o0 = ((vv[u]     - mu) * inv * gw.x + gb.x) * zv.x;
        float o1 = ((vv[u + 1] - mu) * inv * gw.y + gb.y) * zv.y;
        float o2 = ((vv[u + 2] - mu) * inv * gw.z + gb.z) * zv.z;
        float o3 = ((vv[u + 3] - mu) * inv * gw.w + gb.w) * zv.w;
        uint2 hp;
        ((__half2*)&hp)[0] = __halves2half2(__float2half(o0), __float2half(o1));
        ((__half2*)&hp)[1] = __halves2half2(__float2half(o2), __float2half(o3));
        *(uint2*)(g_a_prj1 + row * C_ + cb + u) = hp;
    }
}

// ---------------- launch ----------------
extern "C" void kernel_launch(void* const* d_in, const int* in_sizes, int n_in,
                              void* d_out, int out_size) {
    const float* x       = (const float*)d_in[0];
    const float* w_qkvff = (const float*)d_in[1];
    const float* w_gated = (const float*)d_in[2];
    const float* b_gated = (const float*)d_in[3];
    const float* w_proj  = (const float*)d_in[4];
    const float* b_proj  = (const float*)d_in[5];
    const float* gn_w    = (const float*)d_in[6];
    const float* gn_b    = (const float*)d_in[7];
    const float* w_ff    = (const float*)d_in[8];
    const float* rms_w   = (const float*)d_in[9];
    float* out = (float*)d_out;

    float *p_z, *p_ffout;
    float4* p_rot;
    __half *p_qkv16, *p_a_q1, *p_b_qkv1, *p_a_x1, *p_b_gat1, *p_a_prj1, *p_b_prj1, *p_a_ff1, *p_b_ff1;
    cudaGetSymbolAddress((void**)&p_qkv16, g_qkv16);
    cudaGetSymbolAddress((void**)&p_z,     g_z);
    cudaGetSymbolAddress((void**)&p_ffout, g_ffout);
    cudaGetSymbolAddress((void**)&p_rot,   g_rot);
    cudaGetSymbolAddress((void**)&p_a_q1,  g_a_q1);
    cudaGetSymbolAddress((void**)&p_b_qkv1, g_b_qkv1);
    cudaGetSymbolAddress((void**)&p_a_x1,  g_a_x1);
    cudaGetSymbolAddress((void**)&p_b_gat1, g_b_gat1);
    cudaGetSymbolAddress((void**)&p_a_prj1, g_a_prj1);
    cudaGetSymbolAddress((void**)&p_b_prj1, g_b_prj1);
    cudaGetSymbolAddress((void**)&p_a_ff1, g_a_ff1);
    cudaGetSymbolAddress((void**)&p_b_ff1, g_b_ff1);

    const int SMEM = 1024 + 4 * 49152;               // 197632
    const int ATTN_SMEM = 5 * 64 * 72 * 2 + 256;     // 46336

    static cudaStream_t s1 = nullptr;
    static cudaEvent_t ev0, ev_ax, ev_wq, ev_qkv, ev_gate, ev_ff;
    if (s1 == nullptr) {
        cudaStreamCreateWithFlags(&s1, cudaStreamNonBlocking);
        cudaEventCreateWithFlags(&ev0,     cudaEventDisableTiming);
        cudaEventCreateWithFlags(&ev_ax,   cudaEventDisableTiming);
        cudaEventCreateWithFlags(&ev_wq,   cudaEventDisableTiming);
        cudaEventCreateWithFlags(&ev_qkv,  cudaEventDisableTiming);
        cudaEventCreateWithFlags(&ev_gate, cudaEventDisableTiming);
        cudaEventCreateWithFlags(&ev_ff,   cudaEventDisableTiming);
        cudaFuncSetAttribute(mma_gemm<1>, cudaFuncAttributeMaxDynamicSharedMemorySize, SMEM);
        cudaFuncSetAttribute(mma_gemm<2>, cudaFuncAttributeMaxDynamicSharedMemorySize, SMEM);
        cudaFuncSetAttribute(mma_gemm<3>, cudaFuncAttributeMaxDynamicSharedMemorySize, SMEM);
        cudaFuncSetAttribute(mma_gemm<4>, cudaFuncAttributeMaxDynamicSharedMemorySize, SMEM);
        cudaFuncSetAttribute(mma_gemm<5>, cudaFuncAttributeMaxDynamicSharedMemorySize, SMEM);
        cudaFuncSetAttribute(k_chunk_attn, cudaFuncAttributeMaxDynamicSharedMemorySize, ATTN_SMEM);
    }

    // ---- fork ----
    cudaEventRecord(ev0, 0);
    cudaStreamWaitEvent(s1, ev0, 0);

    // s1: qkvff weight convert FIRST (main waits on ev_wq), then the small converts
    k_half1<<<(C5 * C_) / 1024, 256, 0, s1>>>((const float4*)w_qkvff, p_b_qkv1);
    cudaEventRecord(ev_wq, s1);
    k_half1<<<(C_ * C_) / 1024, 256, 0, s1>>>((const float4*)w_gated, p_b_gat1);
    k_half1<<<(C_ * C_) / 1024, 256, 0, s1>>>((const float4*)w_proj,  p_b_prj1);
    k_half1<<<(C_ * 2 * C_) / 1024, 256, 0, s1>>>((const float4*)w_ff, p_b_ff1);

    // main: rotary table + RMSNorm (concurrent with s1 converts)
    k_rotab<<<(T_ * 512) / 256, 256>>>();
    k_rmsnorm<<<BT, 256>>>(x, rms_w);
    cudaEventRecord(ev_ax, 0);

    // s1: gate GEMM z = silu(x @ w_gated^T + b)
    cudaStreamWaitEvent(s1, ev_ax, 0);
    mma_gemm<1><<<dim3(C_ / 256, BT / 128), 256, SMEM, s1>>>(
        p_a_x1, p_b_gat1, C_, C_, p_z, b_gated, nullptr, nullptr, nullptr);
    cudaEventRecord(ev_gate, s1);

    // s1: ffpart GEMM (B rows 3072..5119) -> gelu fp16 a_ff1
    mma_gemm<4><<<dim3(2 * C_ / 256, BT / 128), 256, SMEM, s1>>>(
        p_a_q1, p_b_qkv1 + (size_t)C3 * C_, C_, 2 * C_,
        nullptr, nullptr, nullptr, nullptr, p_a_ff1);

    // s1: ff GEMM ffout = gelu(ff) @ w_ff^T
    mma_gemm<2><<<dim3(C_ / 256, BT / 128), 256, SMEM, s1>>>(
        p_a_ff1, p_b_ff1, 2 * C_, C_, p_ffout, nullptr, nullptr, nullptr, nullptr);
    cudaEventRecord(ev_ff, s1);

    // main: qkv GEMM with fused xPos rotary -> g_qkv16 fp16 (needs b_qkv1)
    cudaStreamWaitEvent(0, ev_wq, 0);
    mma_gemm<5><<<dim3(C3 / 256, BT / 128), 256, SMEM>>>(
        p_a_q1, p_b_qkv1, C_, C3, nullptr, nullptr, (const float*)p_rot, nullptr, p_qkv16);

    // main: tensor-core attention chain
    k_chunk_kv<<<BH * NC, 256>>>();
    k_scan<<<BH * 4, 256>>>();
    cudaStreamWaitEvent(0, ev_gate, 0);
    k_chunk_attn<<<BH * NC, 256, ATTN_SMEM>>>(gn_w, gn_b);

    // join ff, then final proj GEMM: out = y2 @ w_proj^T + b_proj + x + ffout
    cudaStreamWaitEvent(0, ev_ff, 0);
    mma_gemm<3><<<dim3(C_ / 256, BT / 128), 256, SMEM>>>(
        p_a_prj1, p_b_prj1, C_, C_, out, b_proj, x, p_ffout, nullptr);
}

// round 16
// speedup vs baseline: 1.0500x; 1.0130x over previous
#include <cuda_runtime.h>
#include <cuda_fp16.h>
#include <math.h>
#include <stdint.h>

#define B_  2
#define T_  2048
#define C_  1024
#define H_  16
#define HD  64
#define BT  (B_*T_)      // 4096
#define C3  (3*C_)       // 3072
#define C5  (5*C_)       // 5120
#define NC  (T_/HD)      // 32 chunks
#define BH  (B_*H_)      // 32

// ---------------- scratch (device globals) ----------------
__device__ __half g_qkv16[BT*(size_t)C3];         // q,k,v fp16 (stride 3C), rotary applied
__device__ float  g_W [BH*(size_t)NC*HD*HD];
__device__ __half g_S16[BH*(size_t)NC*HD*HD];     // scanned states fp16
__device__ __half g_z16[BT*(size_t)C_];           // silu(gate) fp16
__device__ __half g_ffout16[BT*(size_t)C_];       // ff GEMM result fp16
__device__ float4 g_rot [T_*(size_t)512];         // (cq,sq,ck,sk) per (t,j)
// single fp16 operands
__device__ __half g_a_q1  [BT*(size_t)C_];        // rms-normed x
__device__ __half g_b_qkv1[C5*(size_t)C_];
__device__ __half g_a_x1  [BT*(size_t)C_];        // raw x
__device__ __half g_b_gat1[C_*(size_t)C_];
__device__ __half g_a_prj1[BT*(size_t)C_];
__device__ __half g_b_prj1[C_*(size_t)C_];
__device__ __half g_a_ff1 [BT*(size_t)2*C_];      // gelu(ff) fp16
__device__ __half g_b_ff1 [C_*(size_t)2*C_];

// ---------------- PTX helpers ----------------
__device__ __forceinline__ uint32_t smem_u32(const void* p) {
    uint32_t a;
    asm("{ .reg .u64 t; cvta.to.shared.u64 t, %1; cvt.u32.u64 %0, t; }" : "=r"(a) : "l"(p));
    return a;
}
#define CPA(dst, src)  asm volatile("cp.async.cg.shared.global [%0], [%1], 16;" :: "r"(dst), "l"(src) : "memory")
#define CPC()          asm volatile("cp.async.commit_group;" ::: "memory")
#define CPW(n)         asm volatile("cp.async.wait_group %0;" :: "n"(n) : "memory")
#define SWZ(o) ((o) ^ (((o) >> 3) & 0x70))

#define LDM_X4(r0, r1, r2, r3, a) \
    asm volatile("ldmatrix.sync.aligned.m8n8.x4.shared.b16 {%0,%1,%2,%3}, [%4];" \
        : "=r"(r0), "=r"(r1), "=r"(r2), "=r"(r3) : "r"(a))
#define LDM_X4T(r0, r1, r2, r3, a) \
    asm volatile("ldmatrix.sync.aligned.m8n8.x4.trans.shared.b16 {%0,%1,%2,%3}, [%4];" \
        : "=r"(r0), "=r"(r1), "=r"(r2), "=r"(r3) : "r"(a))

#define MMA_F16(d, a, b0, b1) \
    asm volatile("mma.sync.aligned.m16n8k16.row.col.f32.f16.f16.f32 " \
        "{%0,%1,%2,%3}, {%4,%5,%6,%7}, {%8,%9}, {%0,%1,%2,%3};" \
        : "+f"((d)[0]), "+f"((d)[1]), "+f"((d)[2]), "+f"((d)[3]) \
        : "r"((a)[0]), "r"((a)[1]), "r"((a)[2]), "r"((a)[3]), "r"(b0), "r"(b1))

// ---------------- warp-MMA fp16 NT GEMM (proven R4 mainloop) ----------------
// EPI 1: silu(v+bias[n]) -> fp16 osplit (row stride N)
// EPI 3: v + bias[n] + aux0[o] + half(osplit[o]) -> fp32 Cout
// EPI 4: gelu(v) -> fp16 osplit (row stride N)
// EPI 5: qkv: fused xPos rotary (n<2048 via aux0 table) -> fp16 osplit (row stride N)
// EPI 6: plain -> fp16 osplit (row stride N)
template<int EPI>
__global__ void __launch_bounds__(256, 1) mma_gemm(
    const __half* __restrict__ A, const __half* __restrict__ Bm,
    int Kp, int N, float* __restrict__ Cout,
    const float* __restrict__ bias, const float* __restrict__ aux0,
    const float* __restrict__ aux1, __half* __restrict__ osplit)
{
    extern __shared__ __align__(1024) char smem_raw[];
    const int S = 4;
    const uint32_t STAGE = 49152;   // A 16KB + B 32KB
    uint32_t sbase = (smem_u32(smem_raw) + 1023) & ~1023u;

    int tid = threadIdx.x;
    int wid = tid >> 5, lane = tid & 31;
    int warp_m = wid & 1, warp_n = wid >> 1;
    int bm = blockIdx.y << 7, bn = blockIdx.x << 8;

    const int nk = Kp >> 6;

    auto load_stage = [&](int s, int k) {
        uint32_t a_s = sbase + s * STAGE;
        uint32_t b_s = a_s + 16384u;
        const __half* Ag = A + (size_t)bm * Kp + (size_t)k * 64;
        const __half* Bg = Bm + (size_t)bn * Kp + (size_t)k * 64;
        #pragma unroll
        for (int q = 0; q < 4; q++) {
            int i = tid + (q << 8);
            int r = i >> 3, c = i & 7;
            uint32_t off = SWZ(r * 128 + c * 16);
            CPA(a_s + off, (const char*)(Ag + (size_t)r * Kp + c * 8));
        }
        #pragma unroll
        for (int q = 0; q < 8; q++) {
            int i = tid + (q << 8);
            int r = i >> 3, c = i & 7;
            uint32_t off = SWZ(r * 128 + c * 16);
            CPA(b_s + off, (const char*)(Bg + (size_t)r * Kp + c * 8));
        }
    };

    float acc[4][8][4];
    #pragma unroll
    for (int mt = 0; mt < 4; mt++)
        #pragma unroll
        for (int nt = 0; nt < 8; nt++)
            #pragma unroll
            for (int u = 0; u < 4; u++) acc[mt][nt][u] = 0.f;

    int j = lane >> 3;
    int lrow = lane & 7;
    int a_row_off = ((j & 1) << 3) + lrow;
    int a_byte_off = (j >> 1) << 4;
    int b_row_off = ((j >> 1) << 3) + lrow;
    int b_byte_off = (j & 1) << 4;

    #pragma unroll
    for (int p = 0; p < S - 1; p++) { load_stage(p, p); CPC(); }

    for (int k = 0; k < nk; k++) {
        CPW(S - 2);
        __syncthreads();
        if (k + S - 1 < nk) load_stage((k + S - 1) % S, k + S - 1);
        CPC();

        uint32_t a_s = sbase + (uint32_t)(k % S) * STAGE;
        uint32_t b_s = a_s + 16384u;
        #pragma unroll
        for (int ks = 0; ks < 4; ks++) {
            uint32_t af[4][4], bf[4][4];
            #pragma unroll
            for (int mt = 0; mt < 4; mt++) {
                int row = warp_m * 64 + mt * 16 + a_row_off;
                uint32_t ad = a_s + SWZ(row * 128 + ks * 32 + a_byte_off);
                LDM_X4(af[mt][0], af[mt][1], af[mt][2], af[mt][3], ad);
            }
            #pragma unroll
            for (int ng = 0; ng < 4; ng++) {
                int row = warp_n * 64 + ng * 16 + b_row_off;
                uint32_t bd = b_s + SWZ(row * 128 + ks * 32 + b_byte_off);
                LDM_X4(bf[ng][0], bf[ng][1], bf[ng][2], bf[ng][3], bd);
            }
            #pragma unroll
            for (int mt = 0; mt < 4; mt++)
                #pragma unroll
                for (int nt = 0; nt < 8; nt++) {
                    uint32_t b0 = bf[nt >> 1][(nt & 1) ? 2 : 0];
                    uint32_t b1 = bf[nt >> 1][(nt & 1) ? 3 : 1];
                    MMA_F16(acc[mt][nt], af[mt], b0, b1);
                }
        }
    }

    // ---------------- epilogue ----------------
    int gid = lane >> 2;
    int tig = lane & 3;
    #pragma unroll
    for (int mt = 0; mt < 4; mt++) {
        int m0 = bm + warp_m * 64 + mt * 16 + gid;
        #pragma unroll
        for (int nt = 0; nt < 8; nt++) {
            int n0 = bn + warp_n * 64 + nt * 8 + tig * 2;
            float* ac = acc[mt][nt];
            #pragma unroll
            for (int half_ = 0; half_ < 2; half_++) {
                int m = m0 + half_ * 8;
                float v0 = ac[half_ * 2], v1 = ac[half_ * 2 + 1];
                if (EPI == 1) {      // silu -> fp16
                    float z0 = v0 + bias[n0], z1 = v1 + bias[n0 + 1];
                    float w0 = z0 / (1.f + expf(-z0));
                    float w1 = z1 / (1.f + expf(-z1));
                    *(__half2*)(osplit + (size_t)m * N + n0) =
                        __halves2half2(__float2half(w0), __float2half(w1));
                } else if (EPI == 3) {   // final: + bias + x + ffout(fp16)
                    size_t o = (size_t)m * N + n0;
                    __half2 fv = *(const __half2*)(osplit + o);
                    float2 w;
                    w.x = v0 + bias[n0]     + aux0[o]     + __half2float(__low2half(fv));
                    w.y = v1 + bias[n0 + 1] + aux0[o + 1] + __half2float(__high2half(fv));
                    *(float2*)&Cout[o] = w;
                } else if (EPI == 4) {  // gelu -> fp16
                    float g0 = 0.5f * v0 * (1.0f + erff(v0 * 0.70710678118654752f));
                    float g1 = 0.5f * v1 * (1.0f + erff(v1 * 0.70710678118654752f));
                    *(__half2*)(osplit + (size_t)m * N + n0) =
                        __halves2half2(__float2half(g0), __float2half(g1));
                } else if (EPI == 5) {  // fused xPos rotary -> fp16
                    float w0 = v0, w1 = v1;
                    if (n0 < 2048) {
                        const float4* rot = (const float4*)aux0;
                        float4 rt = rot[((size_t)(m & (T_ - 1)) << 9) + ((n0 & 1023) >> 1)];
                        float cc = (n0 < 1024) ? rt.x : rt.z;
                        float ss = (n0 < 1024) ? rt.y : rt.w;
                        w0 = v0 * cc - v1 * ss;
                        w1 = v1 * cc + v0 * ss;
                    }
                    *(__half2*)(osplit + (size_t)m * N + n0) =
                        __halves2half2(__float2half(w0), __float2half(w1));
                } else {               // EPI 6: plain -> fp16
                    *(__half2*)(osplit + (size_t)m * N + n0) =
                        __halves2half2(__float2half(v0), __float2half(v1));
                }
            }
        }
    }
}

// ---------------- flat fp32 -> fp16 convert ----------------
__global__ void k_half1(const float4* __restrict__ in, __half* __restrict__ out) {
    int idx = blockIdx.x * 256 + threadIdx.x;
    float4 v = in[idx];
    uint2 hp;
    ((__half2*)&hp)[0] = __halves2half2(__float2half(v.x), __float2half(v.y));
    ((__half2*)&hp)[1] = __halves2half2(__float2half(v.z), __float2half(v.w));
    *(uint2*)(out + (size_t)idx * 4) = hp;
}

// ---------------- rotary table ----------------
__global__ void k_rotab() {
    int idx = blockIdx.x * 256 + threadIdx.x;        // over T_*512
    int t = idx >> 9;
    int j = idx & 511;
    float invf  = powf(10000.0f, -(float)j / 512.0f);
    float theta = (float)t * invf;
    float sn, cs;
    sincosf(theta, &sn, &cs);
    float svec  = (2.0f * (float)j + 0.4f * 1024.0f) / (1.4f * 1024.0f);
    float pw    = ((float)t - 1024.0f) * (1.0f / 512.0f);
    float scale = powf(svec, pw);
    float4 r;
    r.x = cs * scale;  r.y = sn * scale;
    r.z = cs / scale;  r.w = sn / scale;
    g_rot[idx] = r;
}

// ---------------- K1: RMSNorm -> a_q1 fp16, plus raw-x fp16 ----------------
__global__ void k_rmsnorm(const float* __restrict__ x, const float* __restrict__ rms_w) {
    int n = blockIdx.x;
    const float* xr = x + (size_t)n * C_;
    __shared__ float red[256];
    float s = 0.f;
    for (int c = threadIdx.x; c < C_; c += 256) { float v = xr[c]; s += v * v; }
    red[threadIdx.x] = s; __syncthreads();
    for (int o = 128; o > 0; o >>= 1) {
        if (threadIdx.x < o) red[threadIdx.x] += red[threadIdx.x + o];
        __syncthreads();
    }
    float nrm = sqrtf(red[0]) * 0.03125f;
    float inv = 1.0f / fmaxf(nrm, 1e-8f);
    for (int c = threadIdx.x; c < C_; c += 256) {
        float xv = xr[c];
        g_a_q1[(size_t)n * C_ + c] = __float2half(xv * inv * rms_w[c]);
        g_a_x1[(size_t)n * C_ + c] = __float2half(xv);
    }
}

// ---------------- K4: chunk KV summaries via tensor cores ----------------
__global__ void __launch_bounds__(256) k_chunk_kv() {
    __shared__ __align__(16) __half Kd[64 * 72], Vt[64 * 72];
    __shared__ float dec[64];
    int blk = blockIdx.x;
    int bh = blk / NC, c = blk % NC;
    int b = bh / H_, h = bh % H_;
    float gamma = 1.0f - exp2f(-5.0f - (float)h);
    if (threadIdx.x < 64) dec[threadIdx.x] = powf(gamma, (float)(HD - threadIdx.x));
    __syncthreads();
    for (int i = threadIdx.x; i < 4096; i += 256) {
        int j = i >> 6, d = i & 63;
        size_t base = (size_t)(b * T_ + c * HD + j) * C3 + h * HD + d;
        Kd[j * 72 + d] = __float2half(__half2float(g_qkv16[base + C_]) * dec[j]);
        Vt[j * 72 + d] = g_qkv16[base + 2 * C_];
    }
    __syncthreads();
    int wid = threadIdx.x >> 5, lane = threadIdx.x & 31;
    int m0 = (wid & 3) << 4, n0 = (wid >> 2) << 5;
    int jj = lane >> 3, lrow = lane & 7;
    int off1_row = ((jj & 1) << 3) + lrow, off1_byte = (jj >> 1) << 4;
    int off2_row = ((jj >> 1) << 3) + lrow, off2_byte = (jj & 1) << 4;
    uint32_t sK = smem_u32(Kd), sV = smem_u32(Vt);
    const int RS = 144;
    float acc[4][4];
    #pragma unroll
    for (int nt = 0; nt < 4; nt++)
        #pragma unroll
        for (int u = 0; u < 4; u++) acc[nt][u] = 0.f;
    #pragma unroll
    for (int ks = 0; ks < 4; ks++) {
        uint32_t af[4];
        LDM_X4T(af[0], af[1], af[2], af[3],
                sK + (ks * 16 + off2_row) * RS + m0 * 2 + off2_byte);
        #pragma unroll
        for (int nb = 0; nb < 2; nb++) {
            uint32_t bf[4];
            LDM_X4T(bf[0], bf[1], bf[2], bf[3],
                    sV + (ks * 16 + off1_row) * RS + (n0 + nb * 16) * 2 + off1_byte);
            MMA_F16(acc[nb * 2],     af, bf[0], bf[1]);
            MMA_F16(acc[nb * 2 + 1], af, bf[2], bf[3]);
        }
    }
    int gid = lane >> 2, tig = lane & 3;
    float* Wout = g_W + ((size_t)bh * NC + c) * 4096;
    #pragma unroll
    for (int nt = 0; nt < 4; nt++) {
        int e = n0 + nt * 8 + tig * 2;
        #pragma unroll
        for (int hf = 0; hf < 2; hf++) {
            int d = m0 + gid + hf * 8;
            float2 w; w.x = acc[nt][hf * 2]; w.y = acc[nt][hf * 2 + 1];
            *(float2*)&Wout[d * 64 + e] = w;
        }
    }
}

// ---------------- K5: state scan (fp32 state, fp16 output) ----------------
__global__ void k_scan() {
    int blk = blockIdx.x;            // BH*4
    int bh = blk >> 2, part = blk & 3;
    int h = bh % H_;
    float gamma = 1.0f - exp2f(-5.0f - (float)h);
    float g64 = powf(gamma, 64.0f);
    int i = part * 1024 + threadIdx.x * 4;
    float4 st; st.x = st.y = st.z = st.w = 0.f;
    size_t base0 = (size_t)bh * NC * 4096 + i;
    for (int c = 0; c < NC; c++) {
        size_t base = base0 + (size_t)c * 4096;
        uint2 hp;
        ((__half2*)&hp)[0] = __halves2half2(__float2half(st.x), __float2half(st.y));
        ((__half2*)&hp)[1] = __halves2half2(__float2half(st.z), __float2half(st.w));
        *(uint2*)&g_S16[base] = hp;
        float4 w = *(const float4*)&g_W[base];
        st.x = st.x * g64 + w.x;
        st.y = st.y * g64 + w.y;
        st.z = st.z * g64 + w.z;
        st.w = st.w * g64 + w.w;
    }
}

// ---------------- K6: tensor-core chunk attention + fused GN + gate ----------------
__global__ void __launch_bounds__(256) k_chunk_attn(
    const float* __restrict__ gn_w, const float* __restrict__ gn_b) {
    extern __shared__ __align__(16) char smraw[];
    __half* Qs = (__half*)smraw;           // 64*72
    __half* Ks = Qs + 64 * 72;
    __half* Vs = Ks + 64 * 72;
    __half* Ss = Vs + 64 * 72;
    __half* Am = Ss + 64 * 72;
    float* gpow = (float*)(Am + 64 * 72);  // 64
    float* Yb = (float*)smraw;             // aliases Qs+Ks

    int blk = blockIdx.x;
    int bh = blk / NC, c = blk % NC;
    int b = bh / H_, h = bh % H_;
    float gamma = 1.0f - exp2f(-5.0f - (float)h);
    if (threadIdx.x < 64) gpow[threadIdx.x] = powf(gamma, (float)threadIdx.x);
    for (int i = threadIdx.x; i < 4096; i += 256) {
        int j = i >> 6, d = i & 63;
        size_t base = (size_t)(b * T_ + c * HD + j) * C3 + h * HD + d;
        Qs[j * 72 + d] = g_qkv16[base];
        Ks[j * 72 + d] = g_qkv16[base + C_];
        Vs[j * 72 + d] = g_qkv16[base + 2 * C_];
        Ss[j * 72 + d] = g_S16[((size_t)bh * NC + c) * 4096 + i];
    }
    __syncthreads();
    int wid = threadIdx.x >> 5, lane = threadIdx.x & 31;
    int m0 = (wid & 3) << 4, n0 = (wid >> 2) << 5;
    int jj = lane >> 3, lrow = lane & 7;
    int off1_row = ((jj & 1) << 3) + lrow, off1_byte = (jj >> 1) << 4;
    int off2_row = ((jj >> 1) << 3) + lrow, off2_byte = (jj & 1) << 4;
    uint32_t sQ = smem_u32(Qs), sK = smem_u32(Ks), sV = smem_u32(Vs);
    uint32_t sS = smem_u32(Ss), sA = smem_u32(Am);
    const int RS = 144;
    int gid = lane >> 2, tig = lane & 3;

    // ---- phase 1: scores = Q K^T, mask+decay -> Am fp16 ----
    {
        float acc[4][4];
        #pragma unroll
        for (int nt = 0; nt < 4; nt++)
            #pragma unroll
            for (int u = 0; u < 4; u++) acc[nt][u] = 0.f;
        #pragma unroll
        for (int ks = 0; ks < 4; ks++) {
            uint32_t af[4];
            LDM_X4(af[0], af[1], af[2], af[3],
                   sQ + (m0 + off1_row) * RS + ks * 32 + off1_byte);
            #pragma unroll
            for (int nb = 0; nb < 2; nb++) {
                uint32_t bf[4];
                LDM_X4(bf[0], bf[1], bf[2], bf[3],
                       sK + (n0 + nb * 16 + off2_row) * RS + ks * 32 + off2_byte);
                MMA_F16(acc[nb * 2],     af, bf[0], bf[1]);
                MMA_F16(acc[nb * 2 + 1], af, bf[2], bf[3]);
            }
        }
        #pragma unroll
        for (int nt = 0; nt < 4; nt++) {
            int n = n0 + nt * 8 + tig * 2;
            #pragma unroll
            for (int hf = 0; hf < 2; hf++) {
                int i = m0 + gid + hf * 8;
                float v0 = acc[nt][hf * 2], v1 = acc[nt][hf * 2 + 1];
                v0 = (n     <= i) ? v0 * gpow[i - n]     : 0.f;
                v1 = (n + 1 <= i) ? v1 * gpow[i - n - 1] : 0.f;
                *(__half2*)(Am + i * 72 + n) =
                    __halves2half2(__float2half(v0), __float2half(v1));
            }
        }
    }
    __syncthreads();
    // ---- phase 2: Y = Am V + gpow[i] * Q S ----
    float a2[4][4], a3[4][4];
    #pragma unroll
    for (int nt = 0; nt < 4; nt++)
        #pragma unroll
        for (int u = 0; u < 4; u++) { a2[nt][u] = 0.f; a3[nt][u] = 0.f; }
    #pragma unroll
    for (int ks = 0; ks < 4; ks++) {
        uint32_t afA[4], afQ[4];
        LDM_X4(afA[0], afA[1], afA[2], afA[3],
               sA + (m0 + off1_row) * RS + ks * 32 + off1_byte);
        LDM_X4(afQ[0], afQ[1], afQ[2], afQ[3],
               sQ + (m0 + off1_row) * RS + ks * 32 + off1_byte);
        #pragma unroll
        for (int nb = 0; nb < 2; nb++) {
            uint32_t bv[4], bs[4];
            LDM_X4T(bv[0], bv[1], bv[2], bv[3],
                    sV + (ks * 16 + off1_row) * RS + (n0 + nb * 16) * 2 + off1_byte);
            LDM_X4T(bs[0], bs[1], bs[2], bs[3],
                    sS + (ks * 16 + off1_row) * RS + (n0 + nb * 16) * 2 + off1_byte);
            MMA_F16(a2[nb * 2],     afA, bv[0], bv[1]);
            MMA_F16(a2[nb * 2 + 1], afA, bv[2], bv[3]);
            MMA_F16(a3[nb * 2],     afQ, bs[0], bs[1]);
            MMA_F16(a3[nb * 2 + 1], afQ, bs[2], bs[3]);
        }
    }
    __syncthreads();
    #pragma unroll
    for (int nt = 0; nt < 4; nt++) {
        int n = n0 + nt * 8 + tig * 2;
        #pragma unroll
        for (int hf = 0; hf < 2; hf++) {
            int i = m0 + gid + hf * 8;
            float gi = gpow[i];
            Yb[i * 68 + n]     = (a2[nt][hf * 2]     + gi * a3[nt][hf * 2])     * 0.125f;
            Yb[i * 68 + n + 1] = (a2[nt][hf * 2 + 1] + gi * a3[nt][hf * 2 + 1]) * 0.125f;
        }
    }
    __syncthreads();
    // ---- GN + gate (fp16 z) -> a_prj1 fp16 ----
    int i = threadIdx.x >> 2;
    int e0 = (threadIdx.x & 3) << 4;
    float vv[16];
    float sum = 0.f, sq = 0.f;
    #pragma unroll
    for (int u = 0; u < 16; u++) {
        float v = Yb[i * 68 + e0 + u];
        vv[u] = v; sum += v; sq += v * v;
    }
    sum += __shfl_xor_sync(~0u, sum, 1); sq += __shfl_xor_sync(~0u, sq, 1);
    sum += __shfl_xor_sync(~0u, sum, 2); sq += __shfl_xor_sync(~0u, sq, 2);
    float mu  = sum * (1.0f / 64.0f);
    float var = sq * (1.0f / 64.0f) - mu * mu;
    float inv = rsqrtf(var + 1e-5f);
    size_t row = (size_t)(b * T_ + c * HD + i);
    int cb = h * 64 + e0;
    #pragma unroll
    for (int u = 0; u < 16; u += 4) {
        float4 gw = *(const float4*)&gn_w[cb + u];
        float4 gb = *(const float4*)&gn_b[cb + u];
        uint2 zp = *(const uint2*)(g_z16 + row * C_ + cb + u);
        __half2 z01 = ((const __half2*)&zp)[0];
        __half2 z23 = ((const __half2*)&zp)[1];
        float o0 = ((vv[u]     - mu) * inv * gw.x + gb.x) * __half2float(__low2half(z01));
        float o1 = ((vv[u + 1] - mu) * inv * gw.y + gb.y) * __half2float(__high2half(z01));
        float o2 = ((vv[u + 2] - mu) * inv * gw.z + gb.z) * __half2float(__low2half(z23));
        float o3 = ((vv[u + 3] - mu) * inv * gw.w + gb.w) * __half2float(__high2half(z23));
        uint2 hp;
        ((__half2*)&hp)[0] = __halves2half2(__float2half(o0), __float2half(o1));
        ((__half2*)&hp)[1] = __halves2half2(__float2half(o2), __float2half(o3));
        *(uint2*)(g_a_prj1 + row * C_ + cb + u) = hp;
    }
}

// ---------------- launch ----------------
extern "C" void kernel_launch(void* const* d_in, const int* in_sizes, int n_in,
                              void* d_out, int out_size) {
    const float* x       = (const float*)d_in[0];
    const float* w_qkvff = (const float*)d_in[1];
    const float* w_gated = (const float*)d_in[2];
    const float* b_gated = (const float*)d_in[3];
    const float* w_proj  = (const float*)d_in[4];
    const float* b_proj  = (const float*)d_in[5];
    const float* gn_w    = (const float*)d_in[6];
    const float* gn_b    = (const float*)d_in[7];
    const float* w_ff    = (const float*)d_in[8];
    const float* rms_w   = (const float*)d_in[9];
    float* out = (float*)d_out;

    float4* p_rot;
    __half *p_qkv16, *p_z16, *p_ffout16;
    __half *p_a_q1, *p_b_qkv1, *p_a_x1, *p_b_gat1, *p_a_prj1, *p_b_prj1, *p_a_ff1, *p_b_ff1;
    cudaGetSymbolAddress((void**)&p_qkv16, g_qkv16);
    cudaGetSymbolAddress((void**)&p_z16,   g_z16);
    cudaGetSymbolAddress((void**)&p_ffout16, g_ffout16);
    cudaGetSymbolAddress((void**)&p_rot,   g_rot);
    cudaGetSymbolAddress((void**)&p_a_q1,  g_a_q1);
    cudaGetSymbolAddress((void**)&p_b_qkv1, g_b_qkv1);
    cudaGetSymbolAddress((void**)&p_a_x1,  g_a_x1);
    cudaGetSymbolAddress((void**)&p_b_gat1, g_b_gat1);
    cudaGetSymbolAddress((void**)&p_a_prj1, g_a_prj1);
    cudaGetSymbolAddress((void**)&p_b_prj1, g_b_prj1);
    cudaGetSymbolAddress((void**)&p_a_ff1, g_a_ff1);
    cudaGetSymbolAddress((void**)&p_b_ff1, g_b_ff1);

    const int SMEM = 1024 + 4 * 49152;               // 197632
    const int ATTN_SMEM = 5 * 64 * 72 * 2 + 256;     // 46336

    static cudaStream_t s1 = nullptr;
    static cudaEvent_t ev0, ev_ax, ev_wq, ev_gate, ev_ff;
    if (s1 == nullptr) {
        cudaStreamCreateWithFlags(&s1, cudaStreamNonBlocking);
        cudaEventCreateWithFlags(&ev0,     cudaEventDisableTiming);
        cudaEventCreateWithFlags(&ev_ax,   cudaEventDisableTiming);
        cudaEventCreateWithFlags(&ev_wq,   cudaEventDisableTiming);
        cudaEventCreateWithFlags(&ev_gate, cudaEventDisableTiming);
        cudaEventCreateWithFlags(&ev_ff,   cudaEventDisableTiming);
        cudaFuncSetAttribute(mma_gemm<1>, cudaFuncAttributeMaxDynamicSharedMemorySize, SMEM);
        cudaFuncSetAttribute(mma_gemm<3>, cudaFuncAttributeMaxDynamicSharedMemorySize, SMEM);
        cudaFuncSetAttribute(mma_gemm<4>, cudaFuncAttributeMaxDynamicSharedMemorySize, SMEM);
        cudaFuncSetAttribute(mma_gemm<5>, cudaFuncAttributeMaxDynamicSharedMemorySize, SMEM);
        cudaFuncSetAttribute(mma_gemm<6>, cudaFuncAttributeMaxDynamicSharedMemorySize, SMEM);
        cudaFuncSetAttribute(k_chunk_attn, cudaFuncAttributeMaxDynamicSharedMemorySize, ATTN_SMEM);
    }

    // ---- fork ----
    cudaEventRecord(ev0, 0);
    cudaStreamWaitEvent(s1, ev0, 0);

    // s1: qkvff weight convert FIRST (main waits on ev_wq), then the small converts
    k_half1<<<(C5 * C_) / 1024, 256, 0, s1>>>((const float4*)w_qkvff, p_b_qkv1);
    cudaEventRecord(ev_wq, s1);
    k_half1<<<(C_ * C_) / 1024, 256, 0, s1>>>((const float4*)w_gated, p_b_gat1);
    k_half1<<<(C_ * C_) / 1024, 256, 0, s1>>>((const float4*)w_proj,  p_b_prj1);
    k_half1<<<(C_ * 2 * C_) / 1024, 256, 0, s1>>>((const float4*)w_ff, p_b_ff1);

    // main: rotary table + RMSNorm (concurrent with s1 converts)
    k_rotab<<<(T_ * 512) / 256, 256>>>();
    k_rmsnorm<<<BT, 256>>>(x, rms_w);
    cudaEventRecord(ev_ax, 0);

    // s1: gate GEMM z = silu(x @ w_gated^T + b) -> fp16
    cudaStreamWaitEvent(s1, ev_ax, 0);
    mma_gemm<1><<<dim3(C_ / 256, BT / 128), 256, SMEM, s1>>>(
        p_a_x1, p_b_gat1, C_, C_, nullptr, b_gated, nullptr, nullptr, p_z16);
    cudaEventRecord(ev_gate, s1);

    // s1: ffpart GEMM (B rows 3072..5119) -> gelu fp16 a_ff1
    mma_gemm<4><<<dim3(2 * C_ / 256, BT / 128), 256, SMEM, s1>>>(
        p_a_q1, p_b_qkv1 + (size_t)C3 * C_, C_, 2 * C_,
        nullptr, nullptr, nullptr, nullptr, p_a_ff1);

    // s1: ff GEMM ffout = gelu(ff) @ w_ff^T -> fp16
    mma_gemm<6><<<dim3(C_ / 256, BT / 128), 256, SMEM, s1>>>(
        p_a_ff1, p_b_ff1, 2 * C_, C_, nullptr, nullptr, nullptr, nullptr, p_ffout16);
    cudaEventRecord(ev_ff, s1);

    // main: qkv GEMM with fused xPos rotary -> g_qkv16 fp16 (needs b_qkv1)
    cudaStreamWaitEvent(0, ev_wq, 0);
    mma_gemm<5><<<dim3(C3 / 256, BT / 128), 256, SMEM>>>(
        p_a_q1, p_b_qkv1, C_, C3, nullptr, nullptr, (const float*)p_rot, nullptr, p_qkv16);

    // main: tensor-core attention chain
    k_chunk_kv<<<BH * NC, 256>>>();
    k_scan<<<BH * 4, 256>>>();
    cudaStreamWaitEvent(0, ev_gate, 0);
    k_chunk_attn<<<BH * NC, 256, ATTN_SMEM>>>(gn_w, gn_b);

    // join ff, then final proj GEMM: out = y2 @ w_proj^T + b_proj + x + ffout(fp16)
    cudaStreamWaitEvent(0, ev_ff, 0);
    mma_gemm<3><<<dim3(C_ / 256, BT / 128), 256, SMEM>>>(
        p_a_prj1, p_b_prj1, C_, C_, out, b_proj, x, nullptr, p_ffout16);
}